// round 9
// baseline (speedup 1.0000x reference)
#include <cuda_runtime.h>
#include <cuda_bf16.h>
#include <math.h>
#include <stdint.h>

#define SLEN 2048
#define BATCH 64
#define DIN 512
#define DSRC 512
#define DAL 512
#define NTOK (SLEN * BATCH)       // 131072
#define CTX_ELEMS (BATCH * DSRC)  // 32768

// ---------------------------------------------------------------------------
// Scratch (__device__ globals; no cudaMalloc allowed)
// ---------------------------------------------------------------------------
__device__ float g_q[BATCH * DAL];        // input@W1[:, :512]^T + b1
__device__ float g_part[4 * NTOK];        // per-n-tile partial scores [nt][b][s]
__device__ float g_Btf[DAL * DSRC];       // W1[:, 512:] pre-rounded to tf32 (RNA)

// ---------------------------------------------------------------------------
// Helpers
// ---------------------------------------------------------------------------
#define SW128(o) ((o) ^ (((o) >> 3) & 0x70))

__device__ __forceinline__ uint32_t smem_u32(const void* p) {
    uint32_t a;
    asm("{ .reg .u64 t; cvta.to.shared.u64 t, %1; cvt.u32.u64 %0, t; }" : "=r"(a) : "l"(p));
    return a;
}
#define CP16(dst, src) \
    asm volatile("cp.async.cg.shared.global [%0], [%1], 16;" :: "r"(dst), "l"(src))
#define CP_COMMIT() asm volatile("cp.async.commit_group;" ::: "memory")
#define CP_WAIT2() asm volatile("cp.async.wait_group 2;" ::: "memory")
#define CP_WAIT1() asm volatile("cp.async.wait_group 1;" ::: "memory")
#define CP_WAIT0() asm volatile("cp.async.wait_group 0;" ::: "memory")

__device__ __forceinline__ void ldsm4(uint32_t* r, uint32_t addr) {
    asm volatile("ldmatrix.sync.aligned.m8n8.x4.shared.b16 {%0,%1,%2,%3}, [%4];"
                 : "=r"(r[0]), "=r"(r[1]), "=r"(r[2]), "=r"(r[3]) : "r"(addr));
}
// D += A*B, tf32 m16n8k8. a: 4 regs (m16 x k8), b: 2 regs (k8 x n8)
__device__ __forceinline__ void mma_tf32(float* d, const uint32_t* a,
                                         uint32_t b0, uint32_t b1) {
    asm volatile("mma.sync.aligned.m16n8k8.row.col.f32.tf32.tf32.f32 "
                 "{%0,%1,%2,%3}, {%4,%5,%6,%7}, {%8,%9}, {%0,%1,%2,%3};"
                 : "+f"(d[0]), "+f"(d[1]), "+f"(d[2]), "+f"(d[3])
                 : "r"(a[0]), "r"(a[1]), "r"(a[2]), "r"(a[3]), "r"(b0), "r"(b1));
}
__device__ __forceinline__ float to_tf32(float x) {
    uint32_t o;
    asm("cvt.rna.tf32.f32 %0, %1;" : "=r"(o) : "f"(x));
    return __uint_as_float(o);
}

// ---------------------------------------------------------------------------
// Pre-kernel: g_Btf = tf32(W1[:, 512:])   (RNA rounding; 1MB image)
// ---------------------------------------------------------------------------
__global__ __launch_bounds__(256) void k_convB(const float* __restrict__ W1) {
    int u = blockIdx.x * 256 + threadIdx.x;     // 32768 units of 8 elems
    int a = u >> 6, seg = u & 63;
    const float* p = W1 + (size_t)a * (DIN + DSRC) + DIN + seg * 8;
    float* o = g_Btf + a * 512 + seg * 8;
    #pragma unroll
    for (int i = 0; i < 8; i++) o[i] = to_tf32(p[i]);
}

// ---------------------------------------------------------------------------
// Pre-kernel: g_q[b][a] = input[b,:] . W1[a, :512] + b1[a]
// ---------------------------------------------------------------------------
__global__ __launch_bounds__(256) void k_q(const float* __restrict__ inp,
                                           const float* __restrict__ W1,
                                           const float* __restrict__ b1) {
    int gw = blockIdx.x * 8 + (threadIdx.x >> 5);
    int lane = threadIdx.x & 31;
    int b = gw >> 9, a = gw & 511;
    const float* ip = inp + b * DIN;
    const float* wp = W1 + (size_t)a * (DIN + DSRC);
    float s = 0.f;
    #pragma unroll 4
    for (int k = lane; k < DIN; k += 32) s += ip[k] * wp[k];
    #pragma unroll
    for (int o = 16; o; o >>= 1) s += __shfl_xor_sync(0xFFFFFFFFu, s, o);
    if (lane == 0) g_q[b * DAL + a] = s + b1[a];
}

// ---------------------------------------------------------------------------
// Main TF32 HMMA kernel. CTA: M=256 tokens x N=128 aligns, K=512 (16 x k32).
// 8 warps: warp_m = wid&3 (m64), warp_n = wid>>2 (n64) -> 8 ldsm / 32 MMA per k8.
// 4-stage cp.async pipeline (48KB/stage), 1 CTA/SM.
// ldmatrix.x4 B matrix order: b0 n0-7/k0-3, b1 n0-7/k4-7, b2 n8-15/k0-3, b3 n8-15/k4-7
// => n0-7 uses (b[0],b[1]); n8-15 uses (b[2],b[3]).
// ---------------------------------------------------------------------------
#define BUF_A 0
#define BUF_B 32768
#define STAGE_SZ 49152
#define S_W2   196608                     // 4 stages end here
#define S_RED  (S_W2 + 512)               // 256 x 2 floats = 2KB
#define SMEM_TOTAL (S_RED + 2048)         // 199168

__device__ __forceinline__ void issue_stage(uint32_t sb, const float* __restrict__ src,
                                            int t0, int n0, int kc, int stage, int tid) {
    const uint32_t st = sb + stage * STAGE_SZ;
    // A: 2048 16B-units (256 rows x 8 segs) -> 8 per thread
    #pragma unroll
    for (int i = 0; i < 8; i++) {
        const int u = tid + i * 256;
        const int r = u >> 3, s = u & 7;
        const uint32_t d = SW128((uint32_t)(r * 128 + s * 16));
        CP16(st + BUF_A + d, src + (size_t)(t0 + r) * DSRC + kc * 32 + s * 4);
    }
    // B: 1024 16B-units (128 rows x 8 segs) -> 4 per thread
    #pragma unroll
    for (int i = 0; i < 4; i++) {
        const int u = tid + i * 256;
        const int r = u >> 3, s = u & 7;
        const uint32_t d = SW128((uint32_t)(r * 128 + s * 16));
        CP16(st + BUF_B + d, g_Btf + (size_t)(n0 + r) * DSRC + kc * 32 + s * 4);
    }
    CP_COMMIT();
}

__global__ __launch_bounds__(256, 1) void k_main(const float* __restrict__ src,
                                                 const float* __restrict__ W2) {
    extern __shared__ __align__(16) char smem[];
    const uint32_t sb = smem_u32(smem);
    const int tid = threadIdx.x;
    const int lane = tid & 31;
    const int wid = tid >> 5;
    const int warp_m = wid & 3;          // 4 x m64
    const int warp_n = wid >> 2;         // 2 x n64
    const int n0 = blockIdx.x * 128;     // n-tile FAST -> A reuse in L2
    const int t0 = blockIdx.y * 256;

    float acc[4][8][4];
    #pragma unroll
    for (int mt = 0; mt < 4; mt++)
        #pragma unroll
        for (int nt = 0; nt < 8; nt++)
            #pragma unroll
            for (int c = 0; c < 4; c++) acc[mt][nt][c] = 0.f;

    if (tid < 128) ((float*)(smem + S_W2))[tid] = W2[n0 + tid];

    issue_stage(sb, src, t0, n0, 0, 0, tid);
    issue_stage(sb, src, t0, n0, 1, 1, tid);
    issue_stage(sb, src, t0, n0, 2, 2, tid);

    // ldmatrix lane-address components
    const uint32_t a_row = warp_m * 64 + (lane & 15);
    const uint32_t a_kadd = (lane >> 4) * 16;
    const uint32_t b_row = warp_n * 64 + (lane & 7) + ((lane >> 4) & 1) * 8;
    const uint32_t b_kadd = ((lane >> 3) & 1) * 16;

    for (int kc = 0; kc < 16; kc++) {
        if (kc < 14) CP_WAIT2();
        else if (kc == 14) CP_WAIT1();
        else CP_WAIT0();
        __syncthreads();
        if (kc + 3 < 16) issue_stage(sb, src, t0, n0, kc + 3, (kc + 3) & 3, tid);

        const uint32_t st = sb + (kc & 3) * STAGE_SZ;
        #pragma unroll
        for (int ks = 0; ks < 4; ks++) {              // 4 x k8 per chunk
            const uint32_t koff = ks * 32;            // bytes (8 tf32)
            uint32_t a[4][4];
            #pragma unroll
            for (int mt = 0; mt < 4; mt++) {
                uint32_t off = (a_row + mt * 16) * 128 + koff + a_kadd;
                ldsm4(a[mt], st + BUF_A + SW128(off));
            }
            #pragma unroll
            for (int np = 0; np < 4; np++) {
                uint32_t off = (b_row + np * 16) * 128 + koff + b_kadd;
                uint32_t b[4];
                ldsm4(b, st + BUF_B + SW128(off));
                #pragma unroll
                for (int mt = 0; mt < 4; mt++) {
                    mma_tf32(acc[mt][np * 2 + 0], a[mt], b[0], b[1]);
                    mma_tf32(acc[mt][np * 2 + 1], a[mt], b[2], b[3]);
                }
            }
        }
    }
    __syncthreads();   // compute done; stage smem reusable

    // Stage q[b][n0..n0+127] into smem overlay (pad-132 rows)
    float* qs = (float*)smem;
    #pragma unroll
    for (int i = 0; i < 8; i++) {
        int unit = tid + i * 256;         // 2048 float4 units
        int b = unit >> 5, c4 = unit & 31;
        float4 v = *(const float4*)(g_q + b * DAL + n0 + c4 * 4);
        float* d = qs + b * 132 + c4 * 4;
        d[0] = v.x; d[1] = v.y; d[2] = v.z; d[3] = v.w;
    }
    __syncthreads();

    // Epilogue: per-thread tanh + W2 dot, quad-reduce, cross-warp_n combine
    {
        const float* w2s = (const float*)(smem + S_W2);
        float* red = (float*)(smem + S_RED);
        float p[4][2];
        #pragma unroll
        for (int mt = 0; mt < 4; mt++) { p[mt][0] = 0.f; p[mt][1] = 0.f; }
        const int colq = 2 * (lane & 3);
        #pragma unroll
        for (int mt = 0; mt < 4; mt++) {
            #pragma unroll
            for (int nt = 0; nt < 8; nt++) {
                int nloc = warp_n * 64 + nt * 8 + colq;
                float w2a = w2s[nloc], w2b = w2s[nloc + 1];
                #pragma unroll
                for (int h = 0; h < 2; h++) {
                    int rowloc = warp_m * 64 + mt * 16 + h * 8 + (lane >> 2);
                    int b = rowloc & 63;
                    float q0 = qs[b * 132 + nloc];
                    float q1 = qs[b * 132 + nloc + 1];
                    p[mt][h] += w2a * tanhf(acc[mt][nt][h * 2 + 0] + q0)
                              + w2b * tanhf(acc[mt][nt][h * 2 + 1] + q1);
                }
            }
        }
        #pragma unroll
        for (int mt = 0; mt < 4; mt++)
            #pragma unroll
            for (int h = 0; h < 2; h++) {
                p[mt][h] += __shfl_xor_sync(0xFFFFFFFFu, p[mt][h], 1);
                p[mt][h] += __shfl_xor_sync(0xFFFFFFFFu, p[mt][h], 2);
            }
        if ((lane & 3) == 0) {
            #pragma unroll
            for (int mt = 0; mt < 4; mt++)
                #pragma unroll
                for (int h = 0; h < 2; h++) {
                    int rowloc = warp_m * 64 + mt * 16 + h * 8 + (lane >> 2);
                    red[rowloc * 2 + warp_n] = p[mt][h];
                }
        }
        __syncthreads();
        {
            int t = t0 + tid;
            g_part[blockIdx.x * NTOK + (t & 63) * SLEN + (t >> 6)] =
                red[tid * 2] + red[tid * 2 + 1];
        }
    }
}

// ---------------------------------------------------------------------------
// Softmax over S per batch; sums the 4 n-tile partials; attn -> out[CTX + s*B + b]
// ---------------------------------------------------------------------------
__global__ __launch_bounds__(256) void k_softmax(const unsigned char* __restrict__ mask,
                                                 float* __restrict__ out) {
    const int b = blockIdx.x;
    const int tid = threadIdx.x;
    __shared__ float red[256];
    const float* p0 = g_part + 0 * NTOK + b * SLEN;
    const float* p1 = g_part + 1 * NTOK + b * SLEN;
    const float* p2 = g_part + 2 * NTOK + b * SLEN;
    const float* p3 = g_part + 3 * NTOK + b * SLEN;

    float lmax = -INFINITY;
    for (int s = tid; s < SLEN; s += 256) {
        float v = mask[s * BATCH + b] ? -INFINITY : (p0[s] + p1[s] + p2[s] + p3[s]);
        lmax = fmaxf(lmax, v);
    }
    red[tid] = lmax; __syncthreads();
    for (int o = 128; o; o >>= 1) {
        if (tid < o) red[tid] = fmaxf(red[tid], red[tid + o]);
        __syncthreads();
    }
    float m = red[0]; __syncthreads();

    float lsum = 0.f;
    for (int s = tid; s < SLEN; s += 256) {
        float v = mask[s * BATCH + b] ? -INFINITY : (p0[s] + p1[s] + p2[s] + p3[s]);
        lsum += expf(v - m);
    }
    red[tid] = lsum; __syncthreads();
    for (int o = 128; o; o >>= 1) {
        if (tid < o) red[tid] += red[tid + o];
        __syncthreads();
    }
    float inv = 1.f / red[0];

    for (int s = tid; s < SLEN; s += 256) {
        float v = mask[s * BATCH + b] ? -INFINITY : (p0[s] + p1[s] + p2[s] + p3[s]);
        out[CTX_ELEMS + s * BATCH + b] = expf(v - m) * inv;
    }
}

// ---------------------------------------------------------------------------
// ctx[b, d] = sum_s attn[s, b] * src[s, b, d]   (split-S, atomic merge)
// ---------------------------------------------------------------------------
__global__ __launch_bounds__(256) void k_ctx(const float* __restrict__ src,
                                             float* __restrict__ out) {
    const int b = blockIdx.x;
    const int c = blockIdx.y;
    const int tid = threadIdx.x;
    const float* attn = out + CTX_ELEMS;

    float ax = 0.f, ay = 0.f;
    const int s_begin = c * (SLEN / 8);
    const int s_end = s_begin + (SLEN / 8);
    for (int s = s_begin; s < s_end; s += 2) {
        float a0 = attn[s * BATCH + b];
        float a1 = attn[(s + 1) * BATCH + b];
        float2 v0 = *reinterpret_cast<const float2*>(
            src + (size_t)(s * BATCH + b) * DSRC + tid * 2);
        float2 v1 = *reinterpret_cast<const float2*>(
            src + (size_t)((s + 1) * BATCH + b) * DSRC + tid * 2);
        ax += a0 * v0.x + a1 * v1.x;
        ay += a0 * v0.y + a1 * v1.y;
    }
    atomicAdd(&out[b * DSRC + tid * 2 + 0], ax);
    atomicAdd(&out[b * DSRC + tid * 2 + 1], ay);
}

// ---------------------------------------------------------------------------
extern "C" void kernel_launch(void* const* d_in, const int* in_sizes, int n_in,
                              void* d_out, int out_size) {
    const float* inp = (const float*)d_in[0];
    const float* src = (const float*)d_in[1];
    const unsigned char* mask = (const unsigned char*)d_in[2];
    const float* W1 = (const float*)d_in[3];
    const float* b1 = (const float*)d_in[4];
    const float* W2 = (const float*)d_in[5];
    float* out = (float*)d_out;

    cudaFuncSetAttribute(k_main, cudaFuncAttributeMaxDynamicSharedMemorySize, SMEM_TOTAL);

    cudaMemsetAsync(out, 0, CTX_ELEMS * sizeof(float), 0);

    k_convB<<<128, 256>>>(W1);
    k_q<<<4096, 256>>>(inp, W1, b1);

    dim3 gg(4, NTOK / 256);               // n-tile fast, token-tile slow
    k_main<<<gg, 256, SMEM_TOTAL>>>(src, W2);

    k_softmax<<<BATCH, 256>>>(mask, out);
    k_ctx<<<dim3(BATCH, 8), 256>>>(src, out);
}

// round 10
// speedup vs baseline: 1.0439x; 1.0439x over previous
#include <cuda_runtime.h>
#include <cuda_bf16.h>
#include <math.h>
#include <stdint.h>

#define SLEN 2048
#define BATCH 64
#define DIN 512
#define DSRC 512
#define DAL 512
#define NTOK (SLEN * BATCH)       // 131072
#define CTX_ELEMS (BATCH * DSRC)  // 32768

// ---------------------------------------------------------------------------
// Scratch (__device__ globals; no cudaMalloc allowed)
// ---------------------------------------------------------------------------
__device__ float g_q[BATCH * DAL];        // input@W1[:, :512]^T + b1
__device__ float g_part[4 * NTOK];        // per-n-tile partial scores [nt][b][s]
__device__ float g_Btf[DAL * DSRC];       // W1[:, 512:] pre-rounded to tf32 (RNA)

// ---------------------------------------------------------------------------
// Helpers
// ---------------------------------------------------------------------------
#define SW128(o) ((o) ^ (((o) >> 3) & 0x70))

__device__ __forceinline__ uint32_t smem_u32(const void* p) {
    uint32_t a;
    asm("{ .reg .u64 t; cvta.to.shared.u64 t, %1; cvt.u32.u64 %0, t; }" : "=r"(a) : "l"(p));
    return a;
}
#define CP16(dst, src) \
    asm volatile("cp.async.cg.shared.global [%0], [%1], 16;" :: "r"(dst), "l"(src))
#define CP_COMMIT() asm volatile("cp.async.commit_group;" ::: "memory")
#define CP_WAIT1() asm volatile("cp.async.wait_group 1;" ::: "memory")
#define CP_WAIT0() asm volatile("cp.async.wait_group 0;" ::: "memory")

__device__ __forceinline__ void ldsm4(uint32_t* r, uint32_t addr) {
    asm volatile("ldmatrix.sync.aligned.m8n8.x4.shared.b16 {%0,%1,%2,%3}, [%4];"
                 : "=r"(r[0]), "=r"(r[1]), "=r"(r[2]), "=r"(r[3]) : "r"(addr));
}
// D += A*B, tf32 m16n8k8. a: 4 regs (m16 x k8), b: 2 regs (k8 x n8)
__device__ __forceinline__ void mma_tf32(float* d, const uint32_t* a,
                                         uint32_t b0, uint32_t b1) {
    asm volatile("mma.sync.aligned.m16n8k8.row.col.f32.tf32.tf32.f32 "
                 "{%0,%1,%2,%3}, {%4,%5,%6,%7}, {%8,%9}, {%0,%1,%2,%3};"
                 : "+f"(d[0]), "+f"(d[1]), "+f"(d[2]), "+f"(d[3])
                 : "r"(a[0]), "r"(a[1]), "r"(a[2]), "r"(a[3]), "r"(b0), "r"(b1));
}
__device__ __forceinline__ float to_tf32(float x) {
    uint32_t o;
    asm("cvt.rna.tf32.f32 %0, %1;" : "=r"(o) : "f"(x));
    return __uint_as_float(o);
}

// ---------------------------------------------------------------------------
// Pre-kernel: g_Btf = tf32(W1[:, 512:])   (RNA rounding; 1MB image)
// ---------------------------------------------------------------------------
__global__ __launch_bounds__(256) void k_convB(const float* __restrict__ W1) {
    int u = blockIdx.x * 256 + threadIdx.x;     // 32768 units of 8 elems
    int a = u >> 6, seg = u & 63;
    const float* p = W1 + (size_t)a * (DIN + DSRC) + DIN + seg * 8;
    float* o = g_Btf + a * 512 + seg * 8;
    #pragma unroll
    for (int i = 0; i < 8; i++) o[i] = to_tf32(p[i]);
}

// ---------------------------------------------------------------------------
// Pre-kernel: g_q[b][a] = input[b,:] . W1[a, :512] + b1[a]
// ---------------------------------------------------------------------------
__global__ __launch_bounds__(256) void k_q(const float* __restrict__ inp,
                                           const float* __restrict__ W1,
                                           const float* __restrict__ b1) {
    int gw = blockIdx.x * 8 + (threadIdx.x >> 5);
    int lane = threadIdx.x & 31;
    int b = gw >> 9, a = gw & 511;
    const float* ip = inp + b * DIN;
    const float* wp = W1 + (size_t)a * (DIN + DSRC);
    float s = 0.f;
    #pragma unroll 4
    for (int k = lane; k < DIN; k += 32) s += ip[k] * wp[k];
    #pragma unroll
    for (int o = 16; o; o >>= 1) s += __shfl_xor_sync(0xFFFFFFFFu, s, o);
    if (lane == 0) g_q[b * DAL + a] = s + b1[a];
}

// ---------------------------------------------------------------------------
// Main TF32 HMMA kernel. CTA: M=128 x N=128, K=512 (16 x k32), 128 threads.
// 4 warps: warp_m = wid&1 (m64), warp_n = wid>>1 (n64): 8 ldsm / 32 MMA per k8
// (128 B/MMA crossbar) AND 2 CTAs/SM for cross-CTA latency hiding.
// 3-stage cp.async pipeline, 32KB/stage.
// ldmatrix.x4 B matrix order: b0 n0-7/k0-3, b1 n0-7/k4-7, b2 n8-15/k0-3, b3 n8-15/k4-7
// => n0-7 uses (b[0],b[1]); n8-15 uses (b[2],b[3]).
// ---------------------------------------------------------------------------
#define BUF_A 0
#define BUF_B 16384
#define STAGE_SZ 32768
#define S_W2   98304                      // 3 stages end here
#define S_RED  (S_W2 + 512)               // 128 x 2 floats = 1KB
#define SMEM_TOTAL (S_RED + 1024)         // 99840

__device__ __forceinline__ void issue_stage(uint32_t sb, const float* __restrict__ src,
                                            int t0, int n0, int kc, int stage, int tid) {
    const uint32_t st = sb + stage * STAGE_SZ;
    // A and B: 1024 16B-units each (128 rows x 8 segs); 8 per thread per buffer
    #pragma unroll
    for (int i = 0; i < 8; i++) {
        const int u = tid + i * 128;
        const int r = u >> 3, s = u & 7;
        const uint32_t d = SW128((uint32_t)(r * 128 + s * 16));
        CP16(st + BUF_A + d, src + (size_t)(t0 + r) * DSRC + kc * 32 + s * 4);
        CP16(st + BUF_B + d, g_Btf + (size_t)(n0 + r) * DSRC + kc * 32 + s * 4);
    }
    CP_COMMIT();
}

__global__ __launch_bounds__(128, 2) void k_main(const float* __restrict__ src,
                                                 const float* __restrict__ W2) {
    extern __shared__ __align__(16) char smem[];
    const uint32_t sb = smem_u32(smem);
    const int tid = threadIdx.x;
    const int lane = tid & 31;
    const int wid = tid >> 5;
    const int warp_m = wid & 1;          // 2 x m64
    const int warp_n = wid >> 1;         // 2 x n64
    const int n0 = blockIdx.x * 128;     // n-tile FAST -> A reuse in L2
    const int t0 = blockIdx.y * 128;

    float acc[4][8][4];
    #pragma unroll
    for (int mt = 0; mt < 4; mt++)
        #pragma unroll
        for (int nt = 0; nt < 8; nt++)
            #pragma unroll
            for (int c = 0; c < 4; c++) acc[mt][nt][c] = 0.f;

    ((float*)(smem + S_W2))[tid] = W2[n0 + tid];

    issue_stage(sb, src, t0, n0, 0, 0, tid);
    issue_stage(sb, src, t0, n0, 1, 1, tid);

    // ldmatrix lane-address components
    const uint32_t a_row = warp_m * 64 + (lane & 15);
    const uint32_t a_kadd = (lane >> 4) * 16;
    const uint32_t b_row = warp_n * 64 + (lane & 7) + ((lane >> 4) & 1) * 8;
    const uint32_t b_kadd = ((lane >> 3) & 1) * 16;

    for (int kc = 0; kc < 16; kc++) {
        if (kc == 15) CP_WAIT0(); else CP_WAIT1();
        __syncthreads();
        if (kc + 2 < 16) issue_stage(sb, src, t0, n0, kc + 2, (kc + 2) % 3, tid);

        const uint32_t st = sb + (kc % 3) * STAGE_SZ;
        #pragma unroll
        for (int ks = 0; ks < 4; ks++) {              // 4 x k8 per chunk
            const uint32_t koff = ks * 32;            // bytes (8 tf32)
            uint32_t a[4][4];
            #pragma unroll
            for (int mt = 0; mt < 4; mt++) {
                uint32_t off = (a_row + mt * 16) * 128 + koff + a_kadd;
                ldsm4(a[mt], st + BUF_A + SW128(off));
            }
            #pragma unroll
            for (int np = 0; np < 4; np++) {
                uint32_t off = (b_row + np * 16) * 128 + koff + b_kadd;
                uint32_t b[4];
                ldsm4(b, st + BUF_B + SW128(off));
                #pragma unroll
                for (int mt = 0; mt < 4; mt++) {
                    mma_tf32(acc[mt][np * 2 + 0], a[mt], b[0], b[1]);
                    mma_tf32(acc[mt][np * 2 + 1], a[mt], b[2], b[3]);
                }
            }
        }
    }
    __syncthreads();   // compute done; stage smem reusable

    // Stage q[b][n0..n0+127] into smem overlay (pad-132 rows)
    float* qs = (float*)smem;
    #pragma unroll
    for (int i = 0; i < 16; i++) {
        int unit = tid + i * 128;         // 2048 float4 units
        int b = unit >> 5, c4 = unit & 31;
        float4 v = *(const float4*)(g_q + b * DAL + n0 + c4 * 4);
        float* d = qs + b * 132 + c4 * 4;
        d[0] = v.x; d[1] = v.y; d[2] = v.z; d[3] = v.w;
    }
    __syncthreads();

    // Epilogue: per-thread tanh + W2 dot, quad-reduce, cross-warp_n combine
    {
        const float* w2s = (const float*)(smem + S_W2);
        float* red = (float*)(smem + S_RED);
        float p[4][2];
        #pragma unroll
        for (int mt = 0; mt < 4; mt++) { p[mt][0] = 0.f; p[mt][1] = 0.f; }
        const int colq = 2 * (lane & 3);
        #pragma unroll
        for (int mt = 0; mt < 4; mt++) {
            #pragma unroll
            for (int nt = 0; nt < 8; nt++) {
                int nloc = warp_n * 64 + nt * 8 + colq;
                float w2a = w2s[nloc], w2b = w2s[nloc + 1];
                #pragma unroll
                for (int h = 0; h < 2; h++) {
                    int rowloc = warp_m * 64 + mt * 16 + h * 8 + (lane >> 2);
                    int b = rowloc & 63;
                    float q0 = qs[b * 132 + nloc];
                    float q1 = qs[b * 132 + nloc + 1];
                    p[mt][h] += w2a * tanhf(acc[mt][nt][h * 2 + 0] + q0)
                              + w2b * tanhf(acc[mt][nt][h * 2 + 1] + q1);
                }
            }
        }
        #pragma unroll
        for (int mt = 0; mt < 4; mt++)
            #pragma unroll
            for (int h = 0; h < 2; h++) {
                p[mt][h] += __shfl_xor_sync(0xFFFFFFFFu, p[mt][h], 1);
                p[mt][h] += __shfl_xor_sync(0xFFFFFFFFu, p[mt][h], 2);
            }
        if ((lane & 3) == 0) {
            #pragma unroll
            for (int mt = 0; mt < 4; mt++)
                #pragma unroll
                for (int h = 0; h < 2; h++) {
                    int rowloc = warp_m * 64 + mt * 16 + h * 8 + (lane >> 2);
                    red[rowloc * 2 + warp_n] = p[mt][h];
                }
        }
        __syncthreads();
        {
            int t = t0 + tid;
            g_part[blockIdx.x * NTOK + (t & 63) * SLEN + (t >> 6)] =
                red[tid * 2] + red[tid * 2 + 1];
        }
    }
}

// ---------------------------------------------------------------------------
// Softmax over S per batch; sums the 4 n-tile partials; attn -> out[CTX + s*B + b]
// ---------------------------------------------------------------------------
__global__ __launch_bounds__(256) void k_softmax(const unsigned char* __restrict__ mask,
                                                 float* __restrict__ out) {
    const int b = blockIdx.x;
    const int tid = threadIdx.x;
    __shared__ float red[256];
    const float* p0 = g_part + 0 * NTOK + b * SLEN;
    const float* p1 = g_part + 1 * NTOK + b * SLEN;
    const float* p2 = g_part + 2 * NTOK + b * SLEN;
    const float* p3 = g_part + 3 * NTOK + b * SLEN;

    float lmax = -INFINITY;
    for (int s = tid; s < SLEN; s += 256) {
        float v = mask[s * BATCH + b] ? -INFINITY : (p0[s] + p1[s] + p2[s] + p3[s]);
        lmax = fmaxf(lmax, v);
    }
    red[tid] = lmax; __syncthreads();
    for (int o = 128; o; o >>= 1) {
        if (tid < o) red[tid] = fmaxf(red[tid], red[tid + o]);
        __syncthreads();
    }
    float m = red[0]; __syncthreads();

    float lsum = 0.f;
    for (int s = tid; s < SLEN; s += 256) {
        float v = mask[s * BATCH + b] ? -INFINITY : (p0[s] + p1[s] + p2[s] + p3[s]);
        lsum += expf(v - m);
    }
    red[tid] = lsum; __syncthreads();
    for (int o = 128; o; o >>= 1) {
        if (tid < o) red[tid] += red[tid + o];
        __syncthreads();
    }
    float inv = 1.f / red[0];

    for (int s = tid; s < SLEN; s += 256) {
        float v = mask[s * BATCH + b] ? -INFINITY : (p0[s] + p1[s] + p2[s] + p3[s]);
        out[CTX_ELEMS + s * BATCH + b] = expf(v - m) * inv;
    }
}

// ---------------------------------------------------------------------------
// ctx[b, d] = sum_s attn[s, b] * src[s, b, d]   (split-S, atomic merge)
// ---------------------------------------------------------------------------
__global__ __launch_bounds__(256) void k_ctx(const float* __restrict__ src,
                                             float* __restrict__ out) {
    const int b = blockIdx.x;
    const int c = blockIdx.y;
    const int tid = threadIdx.x;
    const float* attn = out + CTX_ELEMS;

    float ax = 0.f, ay = 0.f;
    const int s_begin = c * (SLEN / 8);
    const int s_end = s_begin + (SLEN / 8);
    for (int s = s_begin; s < s_end; s += 2) {
        float a0 = attn[s * BATCH + b];
        float a1 = attn[(s + 1) * BATCH + b];
        float2 v0 = *reinterpret_cast<const float2*>(
            src + (size_t)(s * BATCH + b) * DSRC + tid * 2);
        float2 v1 = *reinterpret_cast<const float2*>(
            src + (size_t)((s + 1) * BATCH + b) * DSRC + tid * 2);
        ax += a0 * v0.x + a1 * v1.x;
        ay += a0 * v0.y + a1 * v1.y;
    }
    atomicAdd(&out[b * DSRC + tid * 2 + 0], ax);
    atomicAdd(&out[b * DSRC + tid * 2 + 1], ay);
}

// ---------------------------------------------------------------------------
extern "C" void kernel_launch(void* const* d_in, const int* in_sizes, int n_in,
                              void* d_out, int out_size) {
    const float* inp = (const float*)d_in[0];
    const float* src = (const float*)d_in[1];
    const unsigned char* mask = (const unsigned char*)d_in[2];
    const float* W1 = (const float*)d_in[3];
    const float* b1 = (const float*)d_in[4];
    const float* W2 = (const float*)d_in[5];
    float* out = (float*)d_out;

    cudaFuncSetAttribute(k_main, cudaFuncAttributeMaxDynamicSharedMemorySize, SMEM_TOTAL);

    cudaMemsetAsync(out, 0, CTX_ELEMS * sizeof(float), 0);

    k_convB<<<128, 256>>>(W1);
    k_q<<<4096, 256>>>(inp, W1, b1);

    dim3 gg(4, NTOK / 128);               // n-tile fast, token-tile slow
    k_main<<<gg, 128, SMEM_TOTAL>>>(src, W2);

    k_softmax<<<BATCH, 256>>>(mask, out);
    k_ctx<<<dim3(BATCH, 8), 256>>>(src, out);
}

// round 12
// speedup vs baseline: 1.3693x; 1.3117x over previous
#include <cuda_runtime.h>
#include <cuda_fp16.h>
#include <math.h>
#include <stdint.h>

#define SLEN 2048
#define BATCH 64
#define DIN 512
#define DSRC 512
#define DAL 512
#define NTOK (SLEN * BATCH)       // 131072
#define CTX_ELEMS (BATCH * DSRC)  // 32768

// ---------------------------------------------------------------------------
// Scratch (__device__ globals; no cudaMalloc allowed)
// ---------------------------------------------------------------------------
__device__ float g_q[BATCH * DAL];               // input@W1[:, :512]^T + b1
__device__ float g_part[4 * NTOK];               // per-n-tile partial scores [nt][b][s]
__device__ __half g_Af16[(size_t)NTOK * DSRC];   // src as fp16 (128MB)
__device__ __half g_Bf16[DAL * DSRC];            // W1[:, 512:] as fp16 (512KB)

// ---------------------------------------------------------------------------
// Helpers
// ---------------------------------------------------------------------------
#define SW128(o) ((o) ^ (((o) >> 3) & 0x70))

__device__ __forceinline__ uint32_t smem_u32(const void* p) {
    uint32_t a;
    asm("{ .reg .u64 t; cvta.to.shared.u64 t, %1; cvt.u32.u64 %0, t; }" : "=r"(a) : "l"(p));
    return a;
}
#define CP16(dst, src) \
    asm volatile("cp.async.cg.shared.global [%0], [%1], 16;" :: "r"(dst), "l"(src))
#define CP_COMMIT() asm volatile("cp.async.commit_group;" ::: "memory")
#define CP_WAIT1() asm volatile("cp.async.wait_group 1;" ::: "memory")
#define CP_WAIT0() asm volatile("cp.async.wait_group 0;" ::: "memory")

__device__ __forceinline__ void ldsm4(uint32_t* r, uint32_t addr) {
    asm volatile("ldmatrix.sync.aligned.m8n8.x4.shared.b16 {%0,%1,%2,%3}, [%4];"
                 : "=r"(r[0]), "=r"(r[1]), "=r"(r[2]), "=r"(r[3]) : "r"(addr));
}
// D += A*B, fp16 m16n8k16, fp32 accum. a: 4 regs, b: 2 regs
__device__ __forceinline__ void mma_f16(float* d, const uint32_t* a,
                                        uint32_t b0, uint32_t b1) {
    asm volatile("mma.sync.aligned.m16n8k16.row.col.f32.f16.f16.f32 "
                 "{%0,%1,%2,%3}, {%4,%5,%6,%7}, {%8,%9}, {%0,%1,%2,%3};"
                 : "+f"(d[0]), "+f"(d[1]), "+f"(d[2]), "+f"(d[3])
                 : "r"(a[0]), "r"(a[1]), "r"(a[2]), "r"(a[3]), "r"(b0), "r"(b1));
}
__device__ __forceinline__ uint32_t h2_bits(__half2 h) {
    uint32_t u;
    memcpy(&u, &h, 4);
    return u;
}
__device__ __forceinline__ uint4 cvt8_f16(float4 v0, float4 v1) {
    uint4 o;
    o.x = h2_bits(__floats2half2_rn(v0.x, v0.y));
    o.y = h2_bits(__floats2half2_rn(v0.z, v0.w));
    o.z = h2_bits(__floats2half2_rn(v1.x, v1.y));
    o.w = h2_bits(__floats2half2_rn(v1.z, v1.w));
    return o;
}

// ---------------------------------------------------------------------------
// Pre-kernel: g_Af16 = fp16(src)   (RN; 128MB image)
// ---------------------------------------------------------------------------
__global__ __launch_bounds__(256) void k_convA(const float* __restrict__ src) {
    size_t u = (size_t)blockIdx.x * 256 + threadIdx.x;   // 8.39M units of 8 elems
    const float* p = src + u * 8;
    float4 v0 = *(const float4*)p;
    float4 v1 = *(const float4*)(p + 4);
    *(uint4*)((char*)g_Af16 + u * 16) = cvt8_f16(v0, v1);
}

// ---------------------------------------------------------------------------
// Pre-kernel: g_Bf16 = fp16(W1[:, 512:])
// ---------------------------------------------------------------------------
__global__ __launch_bounds__(256) void k_convB(const float* __restrict__ W1) {
    int u = blockIdx.x * 256 + threadIdx.x;              // 32768 units of 8 elems
    int a = u >> 6, seg = u & 63;
    const float* p = W1 + (size_t)a * (DIN + DSRC) + DIN + seg * 8;
    float4 v0 = *(const float4*)p;
    float4 v1 = *(const float4*)(p + 4);
    *(uint4*)((char*)g_Bf16 + ((size_t)a * 512 + seg * 8) * 2) = cvt8_f16(v0, v1);
}

// ---------------------------------------------------------------------------
// Pre-kernel: g_q[b][a] = input[b,:] . W1[a, :512] + b1[a]
// ---------------------------------------------------------------------------
__global__ __launch_bounds__(256) void k_q(const float* __restrict__ inp,
                                           const float* __restrict__ W1,
                                           const float* __restrict__ b1) {
    int gw = blockIdx.x * 8 + (threadIdx.x >> 5);
    int lane = threadIdx.x & 31;
    int b = gw >> 9, a = gw & 511;
    const float* ip = inp + b * DIN;
    const float* wp = W1 + (size_t)a * (DIN + DSRC);
    float s = 0.f;
    #pragma unroll 4
    for (int k = lane; k < DIN; k += 32) s += ip[k] * wp[k];
    #pragma unroll
    for (int o = 16; o; o >>= 1) s += __shfl_xor_sync(0xFFFFFFFFu, s, o);
    if (lane == 0) g_q[b * DAL + a] = s + b1[a];
}

// ---------------------------------------------------------------------------
// Main fp16 HMMA kernel. CTA: M=128 x N=128, K=512 (8 x k64), 128 threads.
// 4 warps: warp_m = wid&1 (m64), warp_n = wid>>1 (n64). 2 CTAs/SM.
// 3-stage cp.async pipeline, 32KB/stage (A 16KB + B 16KB, fp16, 128B rows SW128).
// ldmatrix.x4 B matrix order: b0 n0-7/k0-7, b1 n0-7/k8-15, b2 n8-15/k0-7, b3 n8-15/k8-15
// => n0-7 uses (b[0],b[1]); n8-15 uses (b[2],b[3]).
// ---------------------------------------------------------------------------
#define BUF_A 0
#define BUF_B 16384
#define STAGE_SZ 32768
#define S_W2   98304                      // 3 stages end here
#define S_RED  (S_W2 + 512)               // 128 x 2 floats
#define SMEM_TOTAL (S_RED + 1024)         // 99840

__device__ __forceinline__ void issue_stage(uint32_t sb, int t0, int n0, int kc,
                                            int stage, int tid) {
    const uint32_t st = sb + stage * STAGE_SZ;
    // A and B: 1024 16B-units each (128 rows x 8 segs of 8 halves); 8/thread/buffer
    #pragma unroll
    for (int i = 0; i < 8; i++) {
        const int u = tid + i * 128;
        const int r = u >> 3, s = u & 7;
        const uint32_t d = SW128((uint32_t)(r * 128 + s * 16));
        CP16(st + BUF_A + d, g_Af16 + (size_t)(t0 + r) * DSRC + kc * 64 + s * 8);
        CP16(st + BUF_B + d, g_Bf16 + (size_t)(n0 + r) * DSRC + kc * 64 + s * 8);
    }
    CP_COMMIT();
}

__global__ __launch_bounds__(128, 2) void k_main(const float* __restrict__ W2) {
    extern __shared__ __align__(16) char smem[];
    const uint32_t sb = smem_u32(smem);
    const int tid = threadIdx.x;
    const int lane = tid & 31;
    const int wid = tid >> 5;
    const int warp_m = wid & 1;          // 2 x m64
    const int warp_n = wid >> 1;         // 2 x n64
    const int n0 = blockIdx.x * 128;     // n-tile FAST -> A reuse in L2
    const int t0 = blockIdx.y * 128;

    float acc[4][8][4];
    #pragma unroll
    for (int mt = 0; mt < 4; mt++)
        #pragma unroll
        for (int nt = 0; nt < 8; nt++)
            #pragma unroll
            for (int c = 0; c < 4; c++) acc[mt][nt][c] = 0.f;

    ((float*)(smem + S_W2))[tid] = W2[n0 + tid];

    issue_stage(sb, t0, n0, 0, 0, tid);
    issue_stage(sb, t0, n0, 1, 1, tid);

    // ldmatrix lane-address components (fp16: k16 = 32B)
    const uint32_t a_row = warp_m * 64 + (lane & 15);
    const uint32_t a_kadd = (lane >> 4) * 16;
    const uint32_t b_row = warp_n * 64 + (lane & 7) + ((lane >> 4) & 1) * 8;
    const uint32_t b_kadd = ((lane >> 3) & 1) * 16;

    for (int kc = 0; kc < 8; kc++) {
        if (kc == 7) CP_WAIT0(); else CP_WAIT1();
        __syncthreads();
        if (kc + 2 < 8) issue_stage(sb, t0, n0, kc + 2, (kc + 2) % 3, tid);

        const uint32_t st = sb + (kc % 3) * STAGE_SZ;
        #pragma unroll
        for (int ks = 0; ks < 4; ks++) {              // 4 x k16 per chunk
            const uint32_t koff = ks * 32;            // bytes (16 fp16)
            uint32_t a[4][4];
            #pragma unroll
            for (int mt = 0; mt < 4; mt++) {
                uint32_t off = (a_row + mt * 16) * 128 + koff + a_kadd;
                ldsm4(a[mt], st + BUF_A + SW128(off));
            }
            #pragma unroll
            for (int np = 0; np < 4; np++) {
                uint32_t off = (b_row + np * 16) * 128 + koff + b_kadd;
                uint32_t b[4];
                ldsm4(b, st + BUF_B + SW128(off));
                #pragma unroll
                for (int mt = 0; mt < 4; mt++) {
                    mma_f16(acc[mt][np * 2 + 0], a[mt], b[0], b[1]);
                    mma_f16(acc[mt][np * 2 + 1], a[mt], b[2], b[3]);
                }
            }
        }
    }
    __syncthreads();   // compute done; stage smem reusable

    // Stage q[b][n0..n0+127] into smem overlay (pad-132 rows)
    float* qs = (float*)smem;
    #pragma unroll
    for (int i = 0; i < 16; i++) {
        int unit = tid + i * 128;         // 2048 float4 units
        int b = unit >> 5, c4 = unit & 31;
        float4 v = *(const float4*)(g_q + b * DAL + n0 + c4 * 4);
        float* d = qs + b * 132 + c4 * 4;
        d[0] = v.x; d[1] = v.y; d[2] = v.z; d[3] = v.w;
    }
    __syncthreads();

    // Epilogue: per-thread tanh + W2 dot, quad-reduce, cross-warp_n combine
    {
        const float* w2s = (const float*)(smem + S_W2);
        float* red = (float*)(smem + S_RED);
        float p[4][2];
        #pragma unroll
        for (int mt = 0; mt < 4; mt++) { p[mt][0] = 0.f; p[mt][1] = 0.f; }
        const int colq = 2 * (lane & 3);
        #pragma unroll
        for (int mt = 0; mt < 4; mt++) {
            #pragma unroll
            for (int nt = 0; nt < 8; nt++) {
                int nloc = warp_n * 64 + nt * 8 + colq;
                float w2a = w2s[nloc], w2b = w2s[nloc + 1];
                #pragma unroll
                for (int h = 0; h < 2; h++) {
                    int rowloc = warp_m * 64 + mt * 16 + h * 8 + (lane >> 2);
                    int b = rowloc & 63;
                    float q0 = qs[b * 132 + nloc];
                    float q1 = qs[b * 132 + nloc + 1];
                    p[mt][h] += w2a * tanhf(acc[mt][nt][h * 2 + 0] + q0)
                              + w2b * tanhf(acc[mt][nt][h * 2 + 1] + q1);
                }
            }
        }
        #pragma unroll
        for (int mt = 0; mt < 4; mt++)
            #pragma unroll
            for (int h = 0; h < 2; h++) {
                p[mt][h] += __shfl_xor_sync(0xFFFFFFFFu, p[mt][h], 1);
                p[mt][h] += __shfl_xor_sync(0xFFFFFFFFu, p[mt][h], 2);
            }
        if ((lane & 3) == 0) {
            #pragma unroll
            for (int mt = 0; mt < 4; mt++)
                #pragma unroll
                for (int h = 0; h < 2; h++) {
                    int rowloc = warp_m * 64 + mt * 16 + h * 8 + (lane >> 2);
                    red[rowloc * 2 + warp_n] = p[mt][h];
                }
        }
        __syncthreads();
        {
            int t = t0 + tid;
            g_part[blockIdx.x * NTOK + (t & 63) * SLEN + (t >> 6)] =
                red[tid * 2] + red[tid * 2 + 1];
        }
    }
}

// ---------------------------------------------------------------------------
// Softmax over S per batch; sums the 4 n-tile partials; attn -> out[CTX + s*B + b]
// ---------------------------------------------------------------------------
__global__ __launch_bounds__(256) void k_softmax(const unsigned char* __restrict__ mask,
                                                 float* __restrict__ out) {
    const int b = blockIdx.x;
    const int tid = threadIdx.x;
    __shared__ float red[256];
    const float* p0 = g_part + 0 * NTOK + b * SLEN;
    const float* p1 = g_part + 1 * NTOK + b * SLEN;
    const float* p2 = g_part + 2 * NTOK + b * SLEN;
    const float* p3 = g_part + 3 * NTOK + b * SLEN;

    float lmax = -INFINITY;
    for (int s = tid; s < SLEN; s += 256) {
        float v = mask[s * BATCH + b] ? -INFINITY : (p0[s] + p1[s] + p2[s] + p3[s]);
        lmax = fmaxf(lmax, v);
    }
    red[tid] = lmax; __syncthreads();
    for (int o = 128; o; o >>= 1) {
        if (tid < o) red[tid] = fmaxf(red[tid], red[tid + o]);
        __syncthreads();
    }
    float m = red[0]; __syncthreads();

    float lsum = 0.f;
    for (int s = tid; s < SLEN; s += 256) {
        float v = mask[s * BATCH + b] ? -INFINITY : (p0[s] + p1[s] + p2[s] + p3[s]);
        lsum += expf(v - m);
    }
    red[tid] = lsum; __syncthreads();
    for (int o = 128; o; o >>= 1) {
        if (tid < o) red[tid] += red[tid + o];
        __syncthreads();
    }
    float inv = 1.f / red[0];

    for (int s = tid; s < SLEN; s += 256) {
        float v = mask[s * BATCH + b] ? -INFINITY : (p0[s] + p1[s] + p2[s] + p3[s]);
        out[CTX_ELEMS + s * BATCH + b] = expf(v - m) * inv;
    }
}

// ---------------------------------------------------------------------------
// ctx[b, d] = sum_s attn[s, b] * fp16src[s, b, d]   (split-S, atomic merge)
// ---------------------------------------------------------------------------
__global__ __launch_bounds__(256) void k_ctx(float* __restrict__ out) {
    const int b = blockIdx.x;
    const int c = blockIdx.y;
    const int tid = threadIdx.x;
    const float* attn = out + CTX_ELEMS;

    float ax = 0.f, ay = 0.f;
    const int s_begin = c * (SLEN / 8);
    const int s_end = s_begin + (SLEN / 8);
    for (int s = s_begin; s < s_end; s += 2) {
        float a0 = attn[s * BATCH + b];
        float a1 = attn[(s + 1) * BATCH + b];
        float2 v0 = __half22float2(*(const __half2*)(
            g_Af16 + (size_t)(s * BATCH + b) * DSRC + tid * 2));
        float2 v1 = __half22float2(*(const __half2*)(
            g_Af16 + (size_t)((s + 1) * BATCH + b) * DSRC + tid * 2));
        ax += a0 * v0.x + a1 * v1.x;
        ay += a0 * v0.y + a1 * v1.y;
    }
    atomicAdd(&out[b * DSRC + tid * 2 + 0], ax);
    atomicAdd(&out[b * DSRC + tid * 2 + 1], ay);
}

// ---------------------------------------------------------------------------
extern "C" void kernel_launch(void* const* d_in, const int* in_sizes, int n_in,
                              void* d_out, int out_size) {
    const float* inp = (const float*)d_in[0];
    const float* src = (const float*)d_in[1];
    const unsigned char* mask = (const unsigned char*)d_in[2];
    const float* W1 = (const float*)d_in[3];
    const float* b1 = (const float*)d_in[4];
    const float* W2 = (const float*)d_in[5];
    float* out = (float*)d_out;

    cudaFuncSetAttribute(k_main, cudaFuncAttributeMaxDynamicSharedMemorySize, SMEM_TOTAL);

    cudaMemsetAsync(out, 0, CTX_ELEMS * sizeof(float), 0);

    k_convB<<<128, 256>>>(W1);
    k_convA<<<32768, 256>>>(src);
    k_q<<<4096, 256>>>(inp, W1, b1);

    dim3 gg(4, NTOK / 128);               // n-tile fast, token-tile slow
    k_main<<<gg, 128, SMEM_TOTAL>>>(W2);

    k_softmax<<<BATCH, 256>>>(mask, out);
    k_ctx<<<dim3(BATCH, 8), 256>>>(out);
}

// round 13
// speedup vs baseline: 1.4294x; 1.0439x over previous
#include <cuda_runtime.h>
#include <cuda_fp16.h>
#include <math.h>
#include <stdint.h>

#define SLEN 2048
#define BATCH 64
#define DIN 512
#define DSRC 512
#define DAL 512
#define NTOK (SLEN * BATCH)       // 131072
#define CTX_ELEMS (BATCH * DSRC)  // 32768

// ---------------------------------------------------------------------------
// Scratch (__device__ globals; no cudaMalloc allowed)
// ---------------------------------------------------------------------------
__device__ float g_q[BATCH * DAL];               // input@W1[:, :512]^T + b1
__device__ float g_part[4 * NTOK];               // per-n-tile partial scores [nt][b][s]
__device__ __half g_Af16[(size_t)NTOK * DSRC];   // src as fp16 (128MB)
__device__ __half g_Bf16[DAL * DSRC];            // W1[:, 512:] as fp16 (512KB)

// ---------------------------------------------------------------------------
// Helpers
// ---------------------------------------------------------------------------
#define SW128(o) ((o) ^ (((o) >> 3) & 0x70))

__device__ __forceinline__ uint32_t smem_u32(const void* p) {
    uint32_t a;
    asm("{ .reg .u64 t; cvta.to.shared.u64 t, %1; cvt.u32.u64 %0, t; }" : "=r"(a) : "l"(p));
    return a;
}
#define CP16(dst, src) \
    asm volatile("cp.async.cg.shared.global [%0], [%1], 16;" :: "r"(dst), "l"(src))
#define CP_COMMIT() asm volatile("cp.async.commit_group;" ::: "memory")
#define CP_WAIT1() asm volatile("cp.async.wait_group 1;" ::: "memory")
#define CP_WAIT0() asm volatile("cp.async.wait_group 0;" ::: "memory")

__device__ __forceinline__ void ldsm4(uint32_t* r, uint32_t addr) {
    asm volatile("ldmatrix.sync.aligned.m8n8.x4.shared.b16 {%0,%1,%2,%3}, [%4];"
                 : "=r"(r[0]), "=r"(r[1]), "=r"(r[2]), "=r"(r[3]) : "r"(addr));
}
// D += A*B, fp16 m16n8k16, fp32 accum. a: 4 regs, b: 2 regs
__device__ __forceinline__ void mma_f16(float* d, const uint32_t* a,
                                        uint32_t b0, uint32_t b1) {
    asm volatile("mma.sync.aligned.m16n8k16.row.col.f32.f16.f16.f32 "
                 "{%0,%1,%2,%3}, {%4,%5,%6,%7}, {%8,%9}, {%0,%1,%2,%3};"
                 : "+f"(d[0]), "+f"(d[1]), "+f"(d[2]), "+f"(d[3])
                 : "r"(a[0]), "r"(a[1]), "r"(a[2]), "r"(a[3]), "r"(b0), "r"(b1));
}
__device__ __forceinline__ uint32_t h2_bits(__half2 h) {
    uint32_t u;
    memcpy(&u, &h, 4);
    return u;
}
__device__ __forceinline__ uint4 cvt8_f16(float4 v0, float4 v1) {
    uint4 o;
    o.x = h2_bits(__floats2half2_rn(v0.x, v0.y));
    o.y = h2_bits(__floats2half2_rn(v0.z, v0.w));
    o.z = h2_bits(__floats2half2_rn(v1.x, v1.y));
    o.w = h2_bits(__floats2half2_rn(v1.z, v1.w));
    return o;
}

// ---------------------------------------------------------------------------
// Fused pre-kernel: blocks [0,32768) convA, [32768,36864) k_q, [36864,36992) convB
// ---------------------------------------------------------------------------
#define PRE_A_BLOCKS 32768
#define PRE_Q_BLOCKS 4096
#define PRE_B_BLOCKS 128
#define PRE_TOTAL (PRE_A_BLOCKS + PRE_Q_BLOCKS + PRE_B_BLOCKS)

__global__ __launch_bounds__(256) void k_pre(const float* __restrict__ src,
                                             const float* __restrict__ inp,
                                             const float* __restrict__ W1,
                                             const float* __restrict__ b1) {
    const int bx = blockIdx.x;
    const int tid = threadIdx.x;
    if (bx < PRE_A_BLOCKS) {
        // convA: src fp32 -> fp16 image
        size_t u = (size_t)bx * 256 + tid;               // 8.39M units of 8 elems
        const float* p = src + u * 8;
        float4 v0 = *(const float4*)p;
        float4 v1 = *(const float4*)(p + 4);
        *(uint4*)((char*)g_Af16 + u * 16) = cvt8_f16(v0, v1);
    } else if (bx < PRE_A_BLOCKS + PRE_Q_BLOCKS) {
        // k_q: g_q[b][a] = input[b,:] . W1[a, :512] + b1[a]
        int gw = (bx - PRE_A_BLOCKS) * 8 + (tid >> 5);
        int lane = tid & 31;
        int b = gw >> 9, a = gw & 511;
        const float* ip = inp + b * DIN;
        const float* wp = W1 + (size_t)a * (DIN + DSRC);
        float s = 0.f;
        #pragma unroll 4
        for (int k = lane; k < DIN; k += 32) s += ip[k] * wp[k];
        #pragma unroll
        for (int o = 16; o; o >>= 1) s += __shfl_xor_sync(0xFFFFFFFFu, s, o);
        if (lane == 0) g_q[b * DAL + a] = s + b1[a];
    } else {
        // convB: W1[:, 512:] -> fp16 image
        int u = (bx - PRE_A_BLOCKS - PRE_Q_BLOCKS) * 256 + tid;  // 32768 units
        int a = u >> 6, seg = u & 63;
        const float* p = W1 + (size_t)a * (DIN + DSRC) + DIN + seg * 8;
        float4 v0 = *(const float4*)p;
        float4 v1 = *(const float4*)(p + 4);
        *(uint4*)((char*)g_Bf16 + ((size_t)a * 512 + seg * 8) * 2) = cvt8_f16(v0, v1);
    }
}

// ---------------------------------------------------------------------------
// Main fp16 HMMA kernel. CTA: M=128 x N=128, K=512 (8 x k64), 256 threads.
// 8 warps: warp_m = wid&1 (m64), warp_n = wid>>1 (n32) -> 16 warps/SM (2 CTAs).
// 3-stage cp.async pipeline, 32KB/stage. acc 64 regs/thread -> fits 128-reg budget.
// ldmatrix.x4 B matrix order: b0 n0-7/k0-7, b1 n0-7/k8-15, b2 n8-15/k0-7, b3 n8-15/k8-15
// => n0-7 uses (b[0],b[1]); n8-15 uses (b[2],b[3]).
// ---------------------------------------------------------------------------
#define BUF_A 0
#define BUF_B 16384
#define STAGE_SZ 32768
#define S_W2   98304                      // 3 stages end here (512B)
#define S_RED  (S_W2 + 512)               // 128 x 4 floats = 2KB
#define SMEM_TOTAL (S_RED + 2048)         // 100864

__device__ __forceinline__ void issue_stage(uint32_t sb, int t0, int n0, int kc,
                                            int stage, int tid) {
    const uint32_t st = sb + stage * STAGE_SZ;
    // A and B: 1024 16B-units each (128 rows x 8 segs of 8 halves); 4/thread/buffer
    #pragma unroll
    for (int i = 0; i < 4; i++) {
        const int u = tid + i * 256;
        const int r = u >> 3, s = u & 7;
        const uint32_t d = SW128((uint32_t)(r * 128 + s * 16));
        CP16(st + BUF_A + d, g_Af16 + (size_t)(t0 + r) * DSRC + kc * 64 + s * 8);
        CP16(st + BUF_B + d, g_Bf16 + (size_t)(n0 + r) * DSRC + kc * 64 + s * 8);
    }
    CP_COMMIT();
}

__global__ __launch_bounds__(256, 2) void k_main(const float* __restrict__ W2) {
    extern __shared__ __align__(16) char smem[];
    const uint32_t sb = smem_u32(smem);
    const int tid = threadIdx.x;
    const int lane = tid & 31;
    const int wid = tid >> 5;
    const int warp_m = wid & 1;          // 2 x m64
    const int warp_n = wid >> 1;         // 4 x n32
    const int n0 = blockIdx.x * 128;     // n-tile FAST -> A reuse in L2
    const int t0 = blockIdx.y * 128;

    float acc[4][4][4];                  // [mt(m16)][n8 tile][frag]
    #pragma unroll
    for (int mt = 0; mt < 4; mt++)
        #pragma unroll
        for (int nt = 0; nt < 4; nt++)
            #pragma unroll
            for (int c = 0; c < 4; c++) acc[mt][nt][c] = 0.f;

    if (tid < 128) ((float*)(smem + S_W2))[tid] = W2[n0 + tid];

    issue_stage(sb, t0, n0, 0, 0, tid);
    issue_stage(sb, t0, n0, 1, 1, tid);

    // ldmatrix lane-address components (fp16: k16 = 32B)
    const uint32_t a_row = warp_m * 64 + (lane & 15);
    const uint32_t a_kadd = (lane >> 4) * 16;
    const uint32_t b_row = warp_n * 32 + (lane & 7) + ((lane >> 4) & 1) * 8;
    const uint32_t b_kadd = ((lane >> 3) & 1) * 16;

    for (int kc = 0; kc < 8; kc++) {
        if (kc == 7) CP_WAIT0(); else CP_WAIT1();
        __syncthreads();
        if (kc + 2 < 8) issue_stage(sb, t0, n0, kc + 2, (kc + 2) % 3, tid);

        const uint32_t st = sb + (kc % 3) * STAGE_SZ;
        #pragma unroll
        for (int ks = 0; ks < 4; ks++) {              // 4 x k16 per chunk
            const uint32_t koff = ks * 32;            // bytes (16 fp16)
            uint32_t a[4][4];
            #pragma unroll
            for (int mt = 0; mt < 4; mt++) {
                uint32_t off = (a_row + mt * 16) * 128 + koff + a_kadd;
                ldsm4(a[mt], st + BUF_A + SW128(off));
            }
            #pragma unroll
            for (int np = 0; np < 2; np++) {          // 2 x n16
                uint32_t off = (b_row + np * 16) * 128 + koff + b_kadd;
                uint32_t b[4];
                ldsm4(b, st + BUF_B + SW128(off));
                #pragma unroll
                for (int mt = 0; mt < 4; mt++) {
                    mma_f16(acc[mt][np * 2 + 0], a[mt], b[0], b[1]);
                    mma_f16(acc[mt][np * 2 + 1], a[mt], b[2], b[3]);
                }
            }
        }
    }
    __syncthreads();   // compute done; stage smem reusable

    // Stage q[b][n0..n0+127] into smem overlay (pad-132 rows)
    float* qs = (float*)smem;
    #pragma unroll
    for (int i = 0; i < 8; i++) {
        int unit = tid + i * 256;         // 2048 float4 units
        int b = unit >> 5, c4 = unit & 31;
        float4 v = *(const float4*)(g_q + b * DAL + n0 + c4 * 4);
        float* d = qs + b * 132 + c4 * 4;
        d[0] = v.x; d[1] = v.y; d[2] = v.z; d[3] = v.w;
    }
    __syncthreads();

    // Epilogue: per-thread tanh + W2 dot over the warp's n32, quad-reduce,
    // cross-warp_n combine via red[row][4].
    {
        const float* w2s = (const float*)(smem + S_W2);
        float* red = (float*)(smem + S_RED);
        float p[4][2];
        #pragma unroll
        for (int mt = 0; mt < 4; mt++) { p[mt][0] = 0.f; p[mt][1] = 0.f; }
        const int colq = 2 * (lane & 3);
        #pragma unroll
        for (int mt = 0; mt < 4; mt++) {
            #pragma unroll
            for (int nt = 0; nt < 4; nt++) {          // 4 x n8 within n32
                int nloc = warp_n * 32 + nt * 8 + colq;
                float w2a = w2s[nloc], w2b = w2s[nloc + 1];
                #pragma unroll
                for (int h = 0; h < 2; h++) {
                    int rowloc = warp_m * 64 + mt * 16 + h * 8 + (lane >> 2);
                    int b = rowloc & 63;
                    float q0 = qs[b * 132 + nloc];
                    float q1 = qs[b * 132 + nloc + 1];
                    p[mt][h] += w2a * tanhf(acc[mt][nt][h * 2 + 0] + q0)
                              + w2b * tanhf(acc[mt][nt][h * 2 + 1] + q1);
                }
            }
        }
        #pragma unroll
        for (int mt = 0; mt < 4; mt++)
            #pragma unroll
            for (int h = 0; h < 2; h++) {
                p[mt][h] += __shfl_xor_sync(0xFFFFFFFFu, p[mt][h], 1);
                p[mt][h] += __shfl_xor_sync(0xFFFFFFFFu, p[mt][h], 2);
            }
        if ((lane & 3) == 0) {
            #pragma unroll
            for (int mt = 0; mt < 4; mt++)
                #pragma unroll
                for (int h = 0; h < 2; h++) {
                    int rowloc = warp_m * 64 + mt * 16 + h * 8 + (lane >> 2);
                    red[rowloc * 4 + warp_n] = p[mt][h];
                }
        }
        __syncthreads();
        if (tid < 128) {
            int t = t0 + tid;
            g_part[blockIdx.x * NTOK + (t & 63) * SLEN + (t >> 6)] =
                red[tid * 4] + red[tid * 4 + 1] + red[tid * 4 + 2] + red[tid * 4 + 3];
        }
    }
}

// ---------------------------------------------------------------------------
// Softmax over S per batch; sums the 4 n-tile partials; attn -> out[CTX + s*B + b]
// ---------------------------------------------------------------------------
__global__ __launch_bounds__(256) void k_softmax(const unsigned char* __restrict__ mask,
                                                 float* __restrict__ out) {
    const int b = blockIdx.x;
    const int tid = threadIdx.x;
    __shared__ float red[256];
    const float* p0 = g_part + 0 * NTOK + b * SLEN;
    const float* p1 = g_part + 1 * NTOK + b * SLEN;
    const float* p2 = g_part + 2 * NTOK + b * SLEN;
    const float* p3 = g_part + 3 * NTOK + b * SLEN;

    float lmax = -INFINITY;
    for (int s = tid; s < SLEN; s += 256) {
        float v = mask[s * BATCH + b] ? -INFINITY : (p0[s] + p1[s] + p2[s] + p3[s]);
        lmax = fmaxf(lmax, v);
    }
    red[tid] = lmax; __syncthreads();
    for (int o = 128; o; o >>= 1) {
        if (tid < o) red[tid] = fmaxf(red[tid], red[tid + o]);
        __syncthreads();
    }
    float m = red[0]; __syncthreads();

    float lsum = 0.f;
    for (int s = tid; s < SLEN; s += 256) {
        float v = mask[s * BATCH + b] ? -INFINITY : (p0[s] + p1[s] + p2[s] + p3[s]);
        lsum += expf(v - m);
    }
    red[tid] = lsum; __syncthreads();
    for (int o = 128; o; o >>= 1) {
        if (tid < o) red[tid] += red[tid + o];
        __syncthreads();
    }
    float inv = 1.f / red[0];

    for (int s = tid; s < SLEN; s += 256) {
        float v = mask[s * BATCH + b] ? -INFINITY : (p0[s] + p1[s] + p2[s] + p3[s]);
        out[CTX_ELEMS + s * BATCH + b] = expf(v - m) * inv;
    }
}

// ---------------------------------------------------------------------------
// ctx[b, d] = sum_s attn[s, b] * fp16src[s, b, d]   (split-S, atomic merge)
// ---------------------------------------------------------------------------
__global__ __launch_bounds__(256) void k_ctx(float* __restrict__ out) {
    const int b = blockIdx.x;
    const int c = blockIdx.y;
    const int tid = threadIdx.x;
    const float* attn = out + CTX_ELEMS;

    float ax = 0.f, ay = 0.f;
    const int s_begin = c * (SLEN / 8);
    const int s_end = s_begin + (SLEN / 8);
    for (int s = s_begin; s < s_end; s += 2) {
        float a0 = attn[s * BATCH + b];
        float a1 = attn[(s + 1) * BATCH + b];
        float2 v0 = __half22float2(*(const __half2*)(
            g_Af16 + (size_t)(s * BATCH + b) * DSRC + tid * 2));
        float2 v1 = __half22float2(*(const __half2*)(
            g_Af16 + (size_t)((s + 1) * BATCH + b) * DSRC + tid * 2));
        ax += a0 * v0.x + a1 * v1.x;
        ay += a0 * v0.y + a1 * v1.y;
    }
    atomicAdd(&out[b * DSRC + tid * 2 + 0], ax);
    atomicAdd(&out[b * DSRC + tid * 2 + 1], ay);
}

// ---------------------------------------------------------------------------
extern "C" void kernel_launch(void* const* d_in, const int* in_sizes, int n_in,
                              void* d_out, int out_size) {
    const float* inp = (const float*)d_in[0];
    const float* src = (const float*)d_in[1];
    const unsigned char* mask = (const unsigned char*)d_in[2];
    const float* W1 = (const float*)d_in[3];
    const float* b1 = (const float*)d_in[4];
    const float* W2 = (const float*)d_in[5];
    float* out = (float*)d_out;

    cudaFuncSetAttribute(k_main, cudaFuncAttributeMaxDynamicSharedMemorySize, SMEM_TOTAL);

    cudaMemsetAsync(out, 0, CTX_ELEMS * sizeof(float), 0);

    k_pre<<<PRE_TOTAL, 256>>>(src, inp, W1, b1);

    dim3 gg(4, NTOK / 128);               // n-tile fast, token-tile slow
    k_main<<<gg, 256, SMEM_TOTAL>>>(W2);

    k_softmax<<<BATCH, 256>>>(mask, out);
    k_ctx<<<dim3(BATCH, 8), 256>>>(out);
}

// round 15
// speedup vs baseline: 1.5248x; 1.0667x over previous
#include <cuda_runtime.h>
#include <cuda_fp16.h>
#include <math.h>
#include <stdint.h>

#define SLEN 2048
#define BATCH 64
#define DIN 512
#define DSRC 512
#define DAL 512
#define NTOK (SLEN * BATCH)       // 131072
#define CTX_ELEMS (BATCH * DSRC)  // 32768

// ---------------------------------------------------------------------------
// Scratch (__device__ globals; no cudaMalloc allowed)
// ---------------------------------------------------------------------------
__device__ float g_q[BATCH * DAL];               // input@W1[:, :512]^T + b1
__device__ float g_part[4 * NTOK];               // per-n-tile partial scores [nt][b][s]
__device__ __half g_Af16[(size_t)NTOK * DSRC];   // src as fp16 (128MB)
__device__ __half g_Bf16[DAL * DSRC];            // W1[:, 512:] as fp16 (512KB)

// ---------------------------------------------------------------------------
// Helpers
// ---------------------------------------------------------------------------
#define SW128(o) ((o) ^ (((o) >> 3) & 0x70))

__device__ __forceinline__ uint32_t smem_u32(const void* p) {
    uint32_t a;
    asm("{ .reg .u64 t; cvta.to.shared.u64 t, %1; cvt.u32.u64 %0, t; }" : "=r"(a) : "l"(p));
    return a;
}
#define CP16(dst, src) \
    asm volatile("cp.async.cg.shared.global [%0], [%1], 16;" :: "r"(dst), "l"(src))
#define CP_COMMIT() asm volatile("cp.async.commit_group;" ::: "memory")
#define CP_WAIT1() asm volatile("cp.async.wait_group 1;" ::: "memory")
#define CP_WAIT0() asm volatile("cp.async.wait_group 0;" ::: "memory")

__device__ __forceinline__ void ldsm4(uint32_t* r, uint32_t addr) {
    asm volatile("ldmatrix.sync.aligned.m8n8.x4.shared.b16 {%0,%1,%2,%3}, [%4];"
                 : "=r"(r[0]), "=r"(r[1]), "=r"(r[2]), "=r"(r[3]) : "r"(addr));
}
// D += A*B, fp16 m16n8k16, fp32 accum. a: 4 regs, b: 2 regs
__device__ __forceinline__ void mma_f16(float* d, const uint32_t* a,
                                        uint32_t b0, uint32_t b1) {
    asm volatile("mma.sync.aligned.m16n8k16.row.col.f32.f16.f16.f32 "
                 "{%0,%1,%2,%3}, {%4,%5,%6,%7}, {%8,%9}, {%0,%1,%2,%3};"
                 : "+f"(d[0]), "+f"(d[1]), "+f"(d[2]), "+f"(d[3])
                 : "r"(a[0]), "r"(a[1]), "r"(a[2]), "r"(a[3]), "r"(b0), "r"(b1));
}
__device__ __forceinline__ uint32_t h2_bits(__half2 h) {
    uint32_t u;
    memcpy(&u, &h, 4);
    return u;
}
__device__ __forceinline__ uint4 cvt8_f16(float4 v0, float4 v1) {
    uint4 o;
    o.x = h2_bits(__floats2half2_rn(v0.x, v0.y));
    o.y = h2_bits(__floats2half2_rn(v0.z, v0.w));
    o.z = h2_bits(__floats2half2_rn(v1.x, v1.y));
    o.w = h2_bits(__floats2half2_rn(v1.z, v1.w));
    return o;
}

// ---------------------------------------------------------------------------
// Fused pre-kernel: blocks [0,32768) convA, [32768,36864) k_q, [36864,36992) convB
// ---------------------------------------------------------------------------
#define PRE_A_BLOCKS 32768
#define PRE_Q_BLOCKS 4096
#define PRE_B_BLOCKS 128
#define PRE_TOTAL (PRE_A_BLOCKS + PRE_Q_BLOCKS + PRE_B_BLOCKS)

__global__ __launch_bounds__(256) void k_pre(const float* __restrict__ src,
                                             const float* __restrict__ inp,
                                             const float* __restrict__ W1,
                                             const float* __restrict__ b1) {
    const int bx = blockIdx.x;
    const int tid = threadIdx.x;
    if (bx < PRE_A_BLOCKS) {
        size_t u = (size_t)bx * 256 + tid;               // 8.39M units of 8 elems
        const float* p = src + u * 8;
        float4 v0 = *(const float4*)p;
        float4 v1 = *(const float4*)(p + 4);
        *(uint4*)((char*)g_Af16 + u * 16) = cvt8_f16(v0, v1);
    } else if (bx < PRE_A_BLOCKS + PRE_Q_BLOCKS) {
        int gw = (bx - PRE_A_BLOCKS) * 8 + (tid >> 5);
        int lane = tid & 31;
        int b = gw >> 9, a = gw & 511;
        const float* ip = inp + b * DIN;
        const float* wp = W1 + (size_t)a * (DIN + DSRC);
        float s = 0.f;
        #pragma unroll 4
        for (int k = lane; k < DIN; k += 32) s += ip[k] * wp[k];
        #pragma unroll
        for (int o = 16; o; o >>= 1) s += __shfl_xor_sync(0xFFFFFFFFu, s, o);
        if (lane == 0) g_q[b * DAL + a] = s + b1[a];
    } else {
        int u = (bx - PRE_A_BLOCKS - PRE_Q_BLOCKS) * 256 + tid;  // 32768 units
        int a = u >> 6, seg = u & 63;
        const float* p = W1 + (size_t)a * (DIN + DSRC) + DIN + seg * 8;
        float4 v0 = *(const float4*)p;
        float4 v1 = *(const float4*)(p + 4);
        *(uint4*)((char*)g_Bf16 + ((size_t)a * 512 + seg * 8) * 2) = cvt8_f16(v0, v1);
    }
}

// ---------------------------------------------------------------------------
// Main fp16 HMMA kernel (unchanged from round 13).
// CTA: M=128 x N=128, K=512 (8 x k64), 256 threads; 8 warps m64 x n32; 2 CTAs/SM.
// ---------------------------------------------------------------------------
#define BUF_A 0
#define BUF_B 16384
#define STAGE_SZ 32768
#define S_W2   98304
#define S_RED  (S_W2 + 512)
#define SMEM_TOTAL (S_RED + 2048)         // 100864

__device__ __forceinline__ void issue_stage(uint32_t sb, int t0, int n0, int kc,
                                            int stage, int tid) {
    const uint32_t st = sb + stage * STAGE_SZ;
    #pragma unroll
    for (int i = 0; i < 4; i++) {
        const int u = tid + i * 256;
        const int r = u >> 3, s = u & 7;
        const uint32_t d = SW128((uint32_t)(r * 128 + s * 16));
        CP16(st + BUF_A + d, g_Af16 + (size_t)(t0 + r) * DSRC + kc * 64 + s * 8);
        CP16(st + BUF_B + d, g_Bf16 + (size_t)(n0 + r) * DSRC + kc * 64 + s * 8);
    }
    CP_COMMIT();
}

__global__ __launch_bounds__(256, 2) void k_main(const float* __restrict__ W2) {
    extern __shared__ __align__(16) char smem[];
    const uint32_t sb = smem_u32(smem);
    const int tid = threadIdx.x;
    const int lane = tid & 31;
    const int wid = tid >> 5;
    const int warp_m = wid & 1;          // 2 x m64
    const int warp_n = wid >> 1;         // 4 x n32
    const int n0 = blockIdx.x * 128;
    const int t0 = blockIdx.y * 128;

    float acc[4][4][4];
    #pragma unroll
    for (int mt = 0; mt < 4; mt++)
        #pragma unroll
        for (int nt = 0; nt < 4; nt++)
            #pragma unroll
            for (int c = 0; c < 4; c++) acc[mt][nt][c] = 0.f;

    if (tid < 128) ((float*)(smem + S_W2))[tid] = W2[n0 + tid];

    issue_stage(sb, t0, n0, 0, 0, tid);
    issue_stage(sb, t0, n0, 1, 1, tid);

    const uint32_t a_row = warp_m * 64 + (lane & 15);
    const uint32_t a_kadd = (lane >> 4) * 16;
    const uint32_t b_row = warp_n * 32 + (lane & 7) + ((lane >> 4) & 1) * 8;
    const uint32_t b_kadd = ((lane >> 3) & 1) * 16;

    for (int kc = 0; kc < 8; kc++) {
        if (kc == 7) CP_WAIT0(); else CP_WAIT1();
        __syncthreads();
        if (kc + 2 < 8) issue_stage(sb, t0, n0, kc + 2, (kc + 2) % 3, tid);

        const uint32_t st = sb + (kc % 3) * STAGE_SZ;
        #pragma unroll
        for (int ks = 0; ks < 4; ks++) {
            const uint32_t koff = ks * 32;
            uint32_t a[4][4];
            #pragma unroll
            for (int mt = 0; mt < 4; mt++) {
                uint32_t off = (a_row + mt * 16) * 128 + koff + a_kadd;
                ldsm4(a[mt], st + BUF_A + SW128(off));
            }
            #pragma unroll
            for (int np = 0; np < 2; np++) {
                uint32_t off = (b_row + np * 16) * 128 + koff + b_kadd;
                uint32_t b[4];
                ldsm4(b, st + BUF_B + SW128(off));
                #pragma unroll
                for (int mt = 0; mt < 4; mt++) {
                    mma_f16(acc[mt][np * 2 + 0], a[mt], b[0], b[1]);
                    mma_f16(acc[mt][np * 2 + 1], a[mt], b[2], b[3]);
                }
            }
        }
    }
    __syncthreads();

    float* qs = (float*)smem;
    #pragma unroll
    for (int i = 0; i < 8; i++) {
        int unit = tid + i * 256;
        int b = unit >> 5, c4 = unit & 31;
        float4 v = *(const float4*)(g_q + b * DAL + n0 + c4 * 4);
        float* d = qs + b * 132 + c4 * 4;
        d[0] = v.x; d[1] = v.y; d[2] = v.z; d[3] = v.w;
    }
    __syncthreads();

    {
        const float* w2s = (const float*)(smem + S_W2);
        float* red = (float*)(smem + S_RED);
        float p[4][2];
        #pragma unroll
        for (int mt = 0; mt < 4; mt++) { p[mt][0] = 0.f; p[mt][1] = 0.f; }
        const int colq = 2 * (lane & 3);
        #pragma unroll
        for (int mt = 0; mt < 4; mt++) {
            #pragma unroll
            for (int nt = 0; nt < 4; nt++) {
                int nloc = warp_n * 32 + nt * 8 + colq;
                float w2a = w2s[nloc], w2b = w2s[nloc + 1];
                #pragma unroll
                for (int h = 0; h < 2; h++) {
                    int rowloc = warp_m * 64 + mt * 16 + h * 8 + (lane >> 2);
                    int b = rowloc & 63;
                    float q0 = qs[b * 132 + nloc];
                    float q1 = qs[b * 132 + nloc + 1];
                    p[mt][h] += w2a * tanhf(acc[mt][nt][h * 2 + 0] + q0)
                              + w2b * tanhf(acc[mt][nt][h * 2 + 1] + q1);
                }
            }
        }
        #pragma unroll
        for (int mt = 0; mt < 4; mt++)
            #pragma unroll
            for (int h = 0; h < 2; h++) {
                p[mt][h] += __shfl_xor_sync(0xFFFFFFFFu, p[mt][h], 1);
                p[mt][h] += __shfl_xor_sync(0xFFFFFFFFu, p[mt][h], 2);
            }
        if ((lane & 3) == 0) {
            #pragma unroll
            for (int mt = 0; mt < 4; mt++)
                #pragma unroll
                for (int h = 0; h < 2; h++) {
                    int rowloc = warp_m * 64 + mt * 16 + h * 8 + (lane >> 2);
                    red[rowloc * 4 + warp_n] = p[mt][h];
                }
        }
        __syncthreads();
        if (tid < 128) {
            int t = t0 + tid;
            g_part[blockIdx.x * NTOK + (t & 63) * SLEN + (t >> 6)] =
                red[tid * 4] + red[tid * 4 + 1] + red[tid * 4 + 2] + red[tid * 4 + 3];
        }
    }
}

// ---------------------------------------------------------------------------
// Softmax over S per batch. Register-cached: partials read ONCE.
// ---------------------------------------------------------------------------
__global__ __launch_bounds__(256) void k_softmax(const unsigned char* __restrict__ mask,
                                                 float* __restrict__ out) {
    const int b = blockIdx.x;
    const int tid = threadIdx.x;
    __shared__ float red[256];
    const float* p0 = g_part + 0 * NTOK + b * SLEN;
    const float* p1 = g_part + 1 * NTOK + b * SLEN;
    const float* p2 = g_part + 2 * NTOK + b * SLEN;
    const float* p3 = g_part + 3 * NTOK + b * SLEN;

    float v[8];
    float lmax = -INFINITY;
    #pragma unroll
    for (int i = 0; i < 8; i++) {
        int s = tid + i * 256;
        float x = mask[s * BATCH + b] ? -INFINITY : (p0[s] + p1[s] + p2[s] + p3[s]);
        v[i] = x;
        lmax = fmaxf(lmax, x);
    }
    red[tid] = lmax; __syncthreads();
    for (int o = 128; o; o >>= 1) {
        if (tid < o) red[tid] = fmaxf(red[tid], red[tid + o]);
        __syncthreads();
    }
    float m = red[0]; __syncthreads();

    float e[8];
    float lsum = 0.f;
    #pragma unroll
    for (int i = 0; i < 8; i++) {
        e[i] = expf(v[i] - m);
        lsum += e[i];
    }
    red[tid] = lsum; __syncthreads();
    for (int o = 128; o; o >>= 1) {
        if (tid < o) red[tid] += red[tid + o];
        __syncthreads();
    }
    float inv = 1.f / red[0];

    #pragma unroll
    for (int i = 0; i < 8; i++) {
        int s = tid + i * 256;
        out[CTX_ELEMS + s * BATCH + b] = e[i] * inv;
    }
}

// ---------------------------------------------------------------------------
// ctx[b, d] = sum_s attn[s, b] * fp16src[s, b, d]
// grid (64, 32) = 2048 CTAs; 64 s per CTA, unrolled x4 for MLP.
// ---------------------------------------------------------------------------
#define CTX_CHUNKS 32
__global__ __launch_bounds__(256) void k_ctx(float* __restrict__ out) {
    const int b = blockIdx.x;
    const int c = blockIdx.y;
    const int tid = threadIdx.x;
    const float* attn = out + CTX_ELEMS;

    float ax = 0.f, ay = 0.f;
    const int s_begin = c * (SLEN / CTX_CHUNKS);
    #pragma unroll 1
    for (int s = s_begin; s < s_begin + SLEN / CTX_CHUNKS; s += 4) {
        float a0 = attn[(s + 0) * BATCH + b];
        float a1 = attn[(s + 1) * BATCH + b];
        float a2 = attn[(s + 2) * BATCH + b];
        float a3 = attn[(s + 3) * BATCH + b];
        float2 v0 = __half22float2(*(const __half2*)(
            g_Af16 + (size_t)((s + 0) * BATCH + b) * DSRC + tid * 2));
        float2 v1 = __half22float2(*(const __half2*)(
            g_Af16 + (size_t)((s + 1) * BATCH + b) * DSRC + tid * 2));
        float2 v2 = __half22float2(*(const __half2*)(
            g_Af16 + (size_t)((s + 2) * BATCH + b) * DSRC + tid * 2));
        float2 v3 = __half22float2(*(const __half2*)(
            g_Af16 + (size_t)((s + 3) * BATCH + b) * DSRC + tid * 2));
        ax += a0 * v0.x + a1 * v1.x + a2 * v2.x + a3 * v3.x;
        ay += a0 * v0.y + a1 * v1.y + a2 * v2.y + a3 * v3.y;
    }
    atomicAdd(&out[b * DSRC + tid * 2 + 0], ax);
    atomicAdd(&out[b * DSRC + tid * 2 + 1], ay);
}

// ---------------------------------------------------------------------------
extern "C" void kernel_launch(void* const* d_in, const int* in_sizes, int n_in,
                              void* d_out, int out_size) {
    const float* inp = (const float*)d_in[0];
    const float* src = (const float*)d_in[1];
    const unsigned char* mask = (const unsigned char*)d_in[2];
    const float* W1 = (const float*)d_in[3];
    const float* b1 = (const float*)d_in[4];
    const float* W2 = (const float*)d_in[5];
    float* out = (float*)d_out;

    cudaFuncSetAttribute(k_main, cudaFuncAttributeMaxDynamicSharedMemorySize, SMEM_TOTAL);

    cudaMemsetAsync(out, 0, CTX_ELEMS * sizeof(float), 0);

    k_pre<<<PRE_TOTAL, 256>>>(src, inp, W1, b1);

    dim3 gg(4, NTOK / 128);               // n-tile fast, token-tile slow
    k_main<<<gg, 256, SMEM_TOTAL>>>(W2);

    k_softmax<<<BATCH, 256>>>(mask, out);
    k_ctx<<<dim3(BATCH, CTX_CHUNKS), 256>>>(out);
}

// round 16
// speedup vs baseline: 1.6262x; 1.0665x over previous
#include <cuda_runtime.h>
#include <cuda_fp16.h>
#include <math.h>
#include <stdint.h>

#define SLEN 2048
#define BATCH 64
#define DIN 512
#define DSRC 512
#define DAL 512
#define NTOK (SLEN * BATCH)       // 131072
#define CTX_ELEMS (BATCH * DSRC)  // 32768

// ---------------------------------------------------------------------------
// Scratch (__device__ globals; no cudaMalloc allowed)
// ---------------------------------------------------------------------------
__device__ float g_q[BATCH * DAL];               // input@W1[:, :512]^T + b1
__device__ float g_part[4 * NTOK];               // per-n-tile partial scores [nt][b][s]
__device__ __half g_Af16[(size_t)NTOK * DSRC];   // src as fp16 (128MB)
__device__ __half g_Bf16[DAL * DSRC];            // W1[:, 512:] as fp16 (512KB)

// ---------------------------------------------------------------------------
// Helpers
// ---------------------------------------------------------------------------
#define SW128(o) ((o) ^ (((o) >> 3) & 0x70))

__device__ __forceinline__ uint32_t smem_u32(const void* p) {
    uint32_t a;
    asm("{ .reg .u64 t; cvta.to.shared.u64 t, %1; cvt.u32.u64 %0, t; }" : "=r"(a) : "l"(p));
    return a;
}
#define CP16(dst, src) \
    asm volatile("cp.async.cg.shared.global [%0], [%1], 16;" :: "r"(dst), "l"(src))
#define CP_COMMIT() asm volatile("cp.async.commit_group;" ::: "memory")
#define CP_WAIT1() asm volatile("cp.async.wait_group 1;" ::: "memory")
#define CP_WAIT0() asm volatile("cp.async.wait_group 0;" ::: "memory")

__device__ __forceinline__ void ldsm4(uint32_t* r, uint32_t addr) {
    asm volatile("ldmatrix.sync.aligned.m8n8.x4.shared.b16 {%0,%1,%2,%3}, [%4];"
                 : "=r"(r[0]), "=r"(r[1]), "=r"(r[2]), "=r"(r[3]) : "r"(addr));
}
// D += A*B, fp16 m16n8k16, fp32 accum. a: 4 regs, b: 2 regs
__device__ __forceinline__ void mma_f16(float* d, const uint32_t* a,
                                        uint32_t b0, uint32_t b1) {
    asm volatile("mma.sync.aligned.m16n8k16.row.col.f32.f16.f16.f32 "
                 "{%0,%1,%2,%3}, {%4,%5,%6,%7}, {%8,%9}, {%0,%1,%2,%3};"
                 : "+f"(d[0]), "+f"(d[1]), "+f"(d[2]), "+f"(d[3])
                 : "r"(a[0]), "r"(a[1]), "r"(a[2]), "r"(a[3]), "r"(b0), "r"(b1));
}
// Single-MUFU tanh (sm_75+). Max abs err ~2^-10.66 — fine for 1e-3 budget.
__device__ __forceinline__ float fast_tanh(float x) {
    float y;
    asm("tanh.approx.f32 %0, %1;" : "=f"(y) : "f"(x));
    return y;
}
__device__ __forceinline__ uint32_t h2_bits(__half2 h) {
    uint32_t u;
    memcpy(&u, &h, 4);
    return u;
}
__device__ __forceinline__ uint4 cvt8_f16(float4 v0, float4 v1) {
    uint4 o;
    o.x = h2_bits(__floats2half2_rn(v0.x, v0.y));
    o.y = h2_bits(__floats2half2_rn(v0.z, v0.w));
    o.z = h2_bits(__floats2half2_rn(v1.x, v1.y));
    o.w = h2_bits(__floats2half2_rn(v1.z, v1.w));
    return o;
}

// ---------------------------------------------------------------------------
// Fused pre-kernel: blocks [0,32768) convA, [32768,36864) k_q, [36864,36992) convB
// ---------------------------------------------------------------------------
#define PRE_A_BLOCKS 32768
#define PRE_Q_BLOCKS 4096
#define PRE_B_BLOCKS 128
#define PRE_TOTAL (PRE_A_BLOCKS + PRE_Q_BLOCKS + PRE_B_BLOCKS)

__global__ __launch_bounds__(256) void k_pre(const float* __restrict__ src,
                                             const float* __restrict__ inp,
                                             const float* __restrict__ W1,
                                             const float* __restrict__ b1) {
    const int bx = blockIdx.x;
    const int tid = threadIdx.x;
    if (bx < PRE_A_BLOCKS) {
        size_t u = (size_t)bx * 256 + tid;               // 8.39M units of 8 elems
        const float* p = src + u * 8;
        float4 v0 = *(const float4*)p;
        float4 v1 = *(const float4*)(p + 4);
        *(uint4*)((char*)g_Af16 + u * 16) = cvt8_f16(v0, v1);
    } else if (bx < PRE_A_BLOCKS + PRE_Q_BLOCKS) {
        int gw = (bx - PRE_A_BLOCKS) * 8 + (tid >> 5);
        int lane = tid & 31;
        int b = gw >> 9, a = gw & 511;
        const float* ip = inp + b * DIN;
        const float* wp = W1 + (size_t)a * (DIN + DSRC);
        float s = 0.f;
        #pragma unroll 4
        for (int k = lane; k < DIN; k += 32) s += ip[k] * wp[k];
        #pragma unroll
        for (int o = 16; o; o >>= 1) s += __shfl_xor_sync(0xFFFFFFFFu, s, o);
        if (lane == 0) g_q[b * DAL + a] = s + b1[a];
    } else {
        int u = (bx - PRE_A_BLOCKS - PRE_Q_BLOCKS) * 256 + tid;  // 32768 units
        int a = u >> 6, seg = u & 63;
        const float* p = W1 + (size_t)a * (DIN + DSRC) + DIN + seg * 8;
        float4 v0 = *(const float4*)p;
        float4 v1 = *(const float4*)(p + 4);
        *(uint4*)((char*)g_Bf16 + ((size_t)a * 512 + seg * 8) * 2) = cvt8_f16(v0, v1);
    }
}

// ---------------------------------------------------------------------------
// Main fp16 HMMA kernel. CTA: M=128 x N=128, K=512 (8 x k64), 256 threads;
// 8 warps m64 x n32; 2 CTAs/SM; 3-stage cp.async pipeline.
// ---------------------------------------------------------------------------
#define BUF_A 0
#define BUF_B 16384
#define STAGE_SZ 32768
#define S_W2   98304
#define S_RED  (S_W2 + 512)
#define SMEM_TOTAL (S_RED + 2048)         // 100864

__device__ __forceinline__ void issue_stage(uint32_t sb, int t0, int n0, int kc,
                                            int stage, int tid) {
    const uint32_t st = sb + stage * STAGE_SZ;
    #pragma unroll
    for (int i = 0; i < 4; i++) {
        const int u = tid + i * 256;
        const int r = u >> 3, s = u & 7;
        const uint32_t d = SW128((uint32_t)(r * 128 + s * 16));
        CP16(st + BUF_A + d, g_Af16 + (size_t)(t0 + r) * DSRC + kc * 64 + s * 8);
        CP16(st + BUF_B + d, g_Bf16 + (size_t)(n0 + r) * DSRC + kc * 64 + s * 8);
    }
    CP_COMMIT();
}

__global__ __launch_bounds__(256, 2) void k_main(const float* __restrict__ W2) {
    extern __shared__ __align__(16) char smem[];
    const uint32_t sb = smem_u32(smem);
    const int tid = threadIdx.x;
    const int lane = tid & 31;
    const int wid = tid >> 5;
    const int warp_m = wid & 1;          // 2 x m64
    const int warp_n = wid >> 1;         // 4 x n32
    const int n0 = blockIdx.x * 128;
    const int t0 = blockIdx.y * 128;

    float acc[4][4][4];
    #pragma unroll
    for (int mt = 0; mt < 4; mt++)
        #pragma unroll
        for (int nt = 0; nt < 4; nt++)
            #pragma unroll
            for (int c = 0; c < 4; c++) acc[mt][nt][c] = 0.f;

    if (tid < 128) ((float*)(smem + S_W2))[tid] = W2[n0 + tid];

    issue_stage(sb, t0, n0, 0, 0, tid);
    issue_stage(sb, t0, n0, 1, 1, tid);

    const uint32_t a_row = warp_m * 64 + (lane & 15);
    const uint32_t a_kadd = (lane >> 4) * 16;
    const uint32_t b_row = warp_n * 32 + (lane & 7) + ((lane >> 4) & 1) * 8;
    const uint32_t b_kadd = ((lane >> 3) & 1) * 16;

    for (int kc = 0; kc < 8; kc++) {
        if (kc == 7) CP_WAIT0(); else CP_WAIT1();
        __syncthreads();
        if (kc + 2 < 8) issue_stage(sb, t0, n0, kc + 2, (kc + 2) % 3, tid);

        const uint32_t st = sb + (kc % 3) * STAGE_SZ;
        #pragma unroll
        for (int ks = 0; ks < 4; ks++) {
            const uint32_t koff = ks * 32;
            uint32_t a[4][4];
            #pragma unroll
            for (int mt = 0; mt < 4; mt++) {
                uint32_t off = (a_row + mt * 16) * 128 + koff + a_kadd;
                ldsm4(a[mt], st + BUF_A + SW128(off));
            }
            #pragma unroll
            for (int np = 0; np < 2; np++) {
                uint32_t off = (b_row + np * 16) * 128 + koff + b_kadd;
                uint32_t b[4];
                ldsm4(b, st + BUF_B + SW128(off));
                #pragma unroll
                for (int mt = 0; mt < 4; mt++) {
                    mma_f16(acc[mt][np * 2 + 0], a[mt], b[0], b[1]);
                    mma_f16(acc[mt][np * 2 + 1], a[mt], b[2], b[3]);
                }
            }
        }
    }
    __syncthreads();

    float* qs = (float*)smem;
    #pragma unroll
    for (int i = 0; i < 8; i++) {
        int unit = tid + i * 256;
        int b = unit >> 5, c4 = unit & 31;
        float4 v = *(const float4*)(g_q + b * DAL + n0 + c4 * 4);
        float* d = qs + b * 132 + c4 * 4;
        d[0] = v.x; d[1] = v.y; d[2] = v.z; d[3] = v.w;
    }
    __syncthreads();

    {
        const float* w2s = (const float*)(smem + S_W2);
        float* red = (float*)(smem + S_RED);
        float p[4][2];
        #pragma unroll
        for (int mt = 0; mt < 4; mt++) { p[mt][0] = 0.f; p[mt][1] = 0.f; }
        const int colq = 2 * (lane & 3);
        #pragma unroll
        for (int mt = 0; mt < 4; mt++) {
            #pragma unroll
            for (int nt = 0; nt < 4; nt++) {
                int nloc = warp_n * 32 + nt * 8 + colq;
                float w2a = w2s[nloc], w2b = w2s[nloc + 1];
                #pragma unroll
                for (int h = 0; h < 2; h++) {
                    int rowloc = warp_m * 64 + mt * 16 + h * 8 + (lane >> 2);
                    int b = rowloc & 63;
                    float q0 = qs[b * 132 + nloc];
                    float q1 = qs[b * 132 + nloc + 1];
                    p[mt][h] += w2a * fast_tanh(acc[mt][nt][h * 2 + 0] + q0)
                              + w2b * fast_tanh(acc[mt][nt][h * 2 + 1] + q1);
                }
            }
        }
        #pragma unroll
        for (int mt = 0; mt < 4; mt++)
            #pragma unroll
            for (int h = 0; h < 2; h++) {
                p[mt][h] += __shfl_xor_sync(0xFFFFFFFFu, p[mt][h], 1);
                p[mt][h] += __shfl_xor_sync(0xFFFFFFFFu, p[mt][h], 2);
            }
        if ((lane & 3) == 0) {
            #pragma unroll
            for (int mt = 0; mt < 4; mt++)
                #pragma unroll
                for (int h = 0; h < 2; h++) {
                    int rowloc = warp_m * 64 + mt * 16 + h * 8 + (lane >> 2);
                    red[rowloc * 4 + warp_n] = p[mt][h];
                }
        }
        __syncthreads();
        if (tid < 128) {
            int t = t0 + tid;
            g_part[blockIdx.x * NTOK + (t & 63) * SLEN + (t >> 6)] =
                red[tid * 4] + red[tid * 4 + 1] + red[tid * 4 + 2] + red[tid * 4 + 3];
        }
    }
}

// ---------------------------------------------------------------------------
// Softmax over S per batch. Register-cached: partials read ONCE. __expf.
// ---------------------------------------------------------------------------
__global__ __launch_bounds__(256) void k_softmax(const unsigned char* __restrict__ mask,
                                                 float* __restrict__ out) {
    const int b = blockIdx.x;
    const int tid = threadIdx.x;
    __shared__ float red[256];
    const float* p0 = g_part + 0 * NTOK + b * SLEN;
    const float* p1 = g_part + 1 * NTOK + b * SLEN;
    const float* p2 = g_part + 2 * NTOK + b * SLEN;
    const float* p3 = g_part + 3 * NTOK + b * SLEN;

    float v[8];
    float lmax = -INFINITY;
    #pragma unroll
    for (int i = 0; i < 8; i++) {
        int s = tid + i * 256;
        float x = mask[s * BATCH + b] ? -INFINITY : (p0[s] + p1[s] + p2[s] + p3[s]);
        v[i] = x;
        lmax = fmaxf(lmax, x);
    }
    red[tid] = lmax; __syncthreads();
    for (int o = 128; o; o >>= 1) {
        if (tid < o) red[tid] = fmaxf(red[tid], red[tid + o]);
        __syncthreads();
    }
    float m = red[0]; __syncthreads();

    float e[8];
    float lsum = 0.f;
    #pragma unroll
    for (int i = 0; i < 8; i++) {
        e[i] = __expf(v[i] - m);
        lsum += e[i];
    }
    red[tid] = lsum; __syncthreads();
    for (int o = 128; o; o >>= 1) {
        if (tid < o) red[tid] += red[tid + o];
        __syncthreads();
    }
    float inv = 1.f / red[0];

    #pragma unroll
    for (int i = 0; i < 8; i++) {
        int s = tid + i * 256;
        out[CTX_ELEMS + s * BATCH + b] = e[i] * inv;
    }
}

// ---------------------------------------------------------------------------
// ctx[b, d] = sum_s attn[s, b] * fp16src[s, b, d]
// grid (64, 32) = 2048 CTAs; 64 s per CTA, unrolled x8 for MLP.
// ---------------------------------------------------------------------------
#define CTX_CHUNKS 32
__global__ __launch_bounds__(256) void k_ctx(float* __restrict__ out) {
    const int b = blockIdx.x;
    const int c = blockIdx.y;
    const int tid = threadIdx.x;
    const float* attn = out + CTX_ELEMS;

    float ax = 0.f, ay = 0.f;
    const int s_begin = c * (SLEN / CTX_CHUNKS);
    #pragma unroll 1
    for (int s = s_begin; s < s_begin + SLEN / CTX_CHUNKS; s += 8) {
        float a[8];
        float2 v[8];
        #pragma unroll
        for (int j = 0; j < 8; j++) {
            a[j] = attn[(s + j) * BATCH + b];
            v[j] = __half22float2(*(const __half2*)(
                g_Af16 + (size_t)((s + j) * BATCH + b) * DSRC + tid * 2));
        }
        #pragma unroll
        for (int j = 0; j < 8; j++) {
            ax += a[j] * v[j].x;
            ay += a[j] * v[j].y;
        }
    }
    atomicAdd(&out[b * DSRC + tid * 2 + 0], ax);
    atomicAdd(&out[b * DSRC + tid * 2 + 1], ay);
}

// ---------------------------------------------------------------------------
extern "C" void kernel_launch(void* const* d_in, const int* in_sizes, int n_in,
                              void* d_out, int out_size) {
    const float* inp = (const float*)d_in[0];
    const float* src = (const float*)d_in[1];
    const unsigned char* mask = (const unsigned char*)d_in[2];
    const float* W1 = (const float*)d_in[3];
    const float* b1 = (const float*)d_in[4];
    const float* W2 = (const float*)d_in[5];
    float* out = (float*)d_out;

    cudaFuncSetAttribute(k_main, cudaFuncAttributeMaxDynamicSharedMemorySize, SMEM_TOTAL);

    cudaMemsetAsync(out, 0, CTX_ELEMS * sizeof(float), 0);

    k_pre<<<PRE_TOTAL, 256>>>(src, inp, W1, b1);

    dim3 gg(4, NTOK / 128);               // n-tile fast, token-tile slow
    k_main<<<gg, 256, SMEM_TOTAL>>>(W2);

    k_softmax<<<BATCH, 256>>>(mask, out);
    k_ctx<<<dim3(BATCH, CTX_CHUNKS), 256>>>(out);
}